// round 16
// baseline (speedup 1.0000x reference)
#include <cuda_runtime.h>
#include <cuda_fp16.h>
#include <cstdint>

#define BW    2048
#define NTOK  49
#define CDIM  384
#define HEADS 12
#define HD    32
#define NWIN  64

// ---------------------------------------------------------------------------
// Device scratch (allocation-free)
// ---------------------------------------------------------------------------
__device__ __half g_Xh [BW * NTOK * CDIM];          // x, fp16
__device__ __half g_AOh[BW * NTOK * CDIM];          // attention output, fp16
__device__ __half g_W1h[1152 * 384];                // qkv_w^T  [n][k] fp16
__device__ __half g_W2h[384 * 384];                 // proj_w^T [n][k] fp16
__device__ __half g_Qh[BW * HEADS * NTOK * HD];     // fp16, pre-scaled
__device__ __half g_Kh[BW * HEADS * NTOK * HD];
__device__ __half g_Vh[BW * HEADS * NTOK * HD];
__device__ float  g_BM[NWIN * HEADS * NTOK * NTOK]; // bias[rel_idx] + mask

// ---------------------------------------------------------------------------
// Helpers
// ---------------------------------------------------------------------------
__device__ __forceinline__ uint32_t s2u(const void* p) {
    uint32_t a;
    asm("{ .reg .u64 t; cvta.to.shared.u64 t, %1; cvt.u32.u64 %0, t; }"
        : "=r"(a) : "l"(p));
    return a;
}

__device__ __forceinline__ void cp16(uint32_t saddr, const void* g) {
    asm volatile("cp.async.cg.shared.global [%0], [%1], 16;"
                 :: "r"(saddr), "l"(g) : "memory");
}
// .ca variant: also fills L1 — co-resident sibling CTA shares the same A rows.
__device__ __forceinline__ void cp16ca(uint32_t saddr, const void* g) {
    asm volatile("cp.async.ca.shared.global [%0], [%1], 16;"
                 :: "r"(saddr), "l"(g) : "memory");
}
__device__ __forceinline__ void cp_commit() {
    asm volatile("cp.async.commit_group;" ::: "memory");
}
template <int N>
__device__ __forceinline__ void cp_wait() {
    asm volatile("cp.async.wait_group %0;" :: "n"(N) : "memory");
}

// Non-volatile: lets ptxas reorder MMAs against next step's LDSMs.
__device__ __forceinline__ void mma16(float* cc, const unsigned* a, const unsigned* b) {
    asm("mma.sync.aligned.m16n8k16.row.col.f32.f16.f16.f32 "
        "{%0,%1,%2,%3}, {%4,%5,%6,%7}, {%8,%9}, {%0,%1,%2,%3};"
        : "+f"(cc[0]), "+f"(cc[1]), "+f"(cc[2]), "+f"(cc[3])
        : "r"(a[0]), "r"(a[1]), "r"(a[2]), "r"(a[3]), "r"(b[0]), "r"(b[1]));
}

__device__ __forceinline__ void ldsm4(unsigned* d, uint32_t a) {
    asm volatile("ldmatrix.sync.aligned.m8n8.x4.shared.b16 {%0,%1,%2,%3}, [%4];"
                 : "=r"(d[0]), "=r"(d[1]), "=r"(d[2]), "=r"(d[3]) : "r"(a));
}
__device__ __forceinline__ void ldsm2t(unsigned* d, uint32_t a) {
    asm volatile("ldmatrix.sync.aligned.m8n8.x2.trans.shared.b16 {%0,%1}, [%2];"
                 : "=r"(d[0]), "=r"(d[1]) : "r"(a));
}

__device__ __forceinline__ unsigned pack_h2(float a, float b) {
    __half2 h = __floats2half2_rn(a, b);
    return *reinterpret_cast<unsigned*>(&h);
}

// ---------------------------------------------------------------------------
// Merged prep kernel.
// blocks [0, 12544): convert x -> fp16, 2 float4 reads -> 1 uint4 store/thread
// blocks [12544, 14080): weight transpose
// blocks [14080, 14848): bias+mask table
// ---------------------------------------------------------------------------
#define XB_XH 12544
#define XB_WT (XB_XH + 1536)

__global__ void __launch_bounds__(384) prep_all(const float* __restrict__ x,
                                                const float* __restrict__ w1,
                                                const float* __restrict__ w2,
                                                const float* __restrict__ mask,
                                                const float* __restrict__ bt,
                                                const int* __restrict__ ri) {
    const int blk = blockIdx.x;
    if (blk < XB_XH) {
        const int i = blk * 384 + threadIdx.x;       // 0 .. 4816895
        float4 a = ((const float4*)x)[2 * i];
        float4 b = ((const float4*)x)[2 * i + 1];
        uint4 o;
        o.x = pack_h2(a.x, a.y);
        o.y = pack_h2(a.z, a.w);
        o.z = pack_h2(b.x, b.y);
        o.w = pack_h2(b.z, b.w);
        ((uint4*)g_Xh)[i] = o;
    } else if (blk < XB_WT) {
        const int b2 = blk - XB_XH;                  // 0..1535
        const int k = threadIdx.x;
        if (b2 < 1152) {
            g_W1h[b2 * 384 + k] = __float2half_rn(w1[k * 1152 + b2]);
        } else {
            const int n = b2 - 1152;
            g_W2h[n * 384 + k] = __float2half_rn(w2[k * 384 + n]);
        }
    } else {
        const int b3 = blk - XB_WT;                  // 0..767
        const int w = b3 & 63, h = b3 >> 6;
        float* dst = g_BM + (w * HEADS + h) * (NTOK * NTOK);
        const float* mw = mask + w * (NTOK * NTOK);
        for (int i = threadIdx.x; i < NTOK * NTOK; i += 384)
            dst[i] = bt[ri[i] * HEADS + h] + mw[i];
    }
}

// ---------------------------------------------------------------------------
// fp16 mma.sync GEMM, BK=32, 5-stage cp.async ring, prefetch distance 4.
// Each CTA processes TWO 128-row tiles through ONE continuous 24-ktile
// pipeline; tile-0 epilogue fires at g==11 while tile-1 chunks are already
// in flight. BM=128/tile, BN=128; 256 threads, 8 warps (2m x 4n), warp
// tile 64x32. __launch_bounds__(256,2) -> 2 CTAs/SM.
// ---------------------------------------------------------------------------
#define STG_B  16384      // A 8KB + B 8KB per stage
#define NSTG   5
#define DYNSZ  (NSTG * STG_B)
#define TILE_A_OFF (128 * 384)   // halfs between row tiles

template <int EPI>
__global__ void __launch_bounds__(256, 2) gemm_h(const float* __restrict__ bias,
                                                 float* __restrict__ out) {
    extern __shared__ char smem[];
    const uint32_t smem0 = s2u(smem);

    const __half* A  = (EPI == 0) ? g_Xh : g_AOh;
    const __half* Bw = (EPI == 0) ? (const __half*)g_W1h : (const __half*)g_W2h;

    const int tid  = threadIdx.x;
    const int lane = tid & 31;
    const int warp = tid >> 5;
    const int wm   = warp >> 2;           // 0..1 -> m = wm*64
    const int wn   = warp & 3;            // 0..3 -> n = wn*32
    const int colBase = blockIdx.x * 128;
    const int rowBase = blockIdx.y * 256;   // two 128-row tiles

    const __half* Ag = A + (size_t)rowBase * 384;
    const __half* Bg = Bw + (size_t)colBase * 384;

    const int r0 = tid >> 2,          c0 = tid & 3;
    const int r1 = (tid + 256) >> 2,  c1 = (tid + 256) & 3;

    // g = global ktile 0..23; tile = g/12, ktile-in-tile = g%12
#define LOADSTG(s, g)                                                           \
    do {                                                                        \
        const int tt_ = (g) >= 12 ? 1 : 0;                                      \
        const int kk_ = (g) - tt_ * 12;                                         \
        const __half* Agx = Ag + tt_ * TILE_A_OFF;                              \
        const uint32_t sb = smem0 + (s) * STG_B;                                \
        cp16ca(sb + c0 * 2048 + r0 * 16, Agx + r0 * 384 + kk_ * 32 + c0 * 8);   \
        cp16ca(sb + c1 * 2048 + r1 * 16, Agx + r1 * 384 + kk_ * 32 + c1 * 8);   \
        cp16(sb + 8192 + c0 * 2048 + r0 * 16,                                   \
             Bg + r0 * 384 + kk_ * 32 + c0 * 8);                                \
        cp16(sb + 8192 + c1 * 2048 + r1 * 16,                                   \
             Bg + r1 * 384 + kk_ * 32 + c1 * 8);                                \
    } while (0)

    float acc[4][4][4];
#pragma unroll
    for (int mi = 0; mi < 4; mi++)
#pragma unroll
        for (int ni = 0; ni < 4; ni++)
#pragma unroll
            for (int k = 0; k < 4; k++) acc[mi][ni][k] = 0.f;

    LOADSTG(0, 0);
    cp_commit();
    LOADSTG(1, 1);
    cp_commit();
    LOADSTG(2, 2);
    cp_commit();
    LOADSTG(3, 3);
    cp_commit();

    const int r = lane >> 2;
    const int c = lane & 3;
    const int lr = lane & 7, sel = lane >> 3;
    const uint32_t a_lane = (uint32_t)((lr + (sel & 1) * 8) * 16 + (sel >> 1) * 2048);
    const uint32_t b_lane = (uint32_t)(((sel >> 1) * 8 + lr) * 16 + (sel & 1) * 2048);

    // epilogue for the tile whose 128-row base is rowB (uses current acc)
#define EPILOG(rowB)                                                                 \
    do {                                                                             \
        _Pragma("unroll")                                                            \
        for (int mi = 0; mi < 4; mi++) {                                             \
            _Pragma("unroll")                                                        \
            for (int g2 = 0; g2 < 2; g2++) {                                         \
                const int row = (rowB) + wm * 64 + mi * 16 + r + g2 * 8;             \
                int bb = 0, n = 0;                                                   \
                if (EPI == 0) { bb = row / 49; n = row - bb * 49; }                  \
                _Pragma("unroll")                                                    \
                for (int ni = 0; ni < 4; ni++) {                                     \
                    const int col = colBase + wn * 32 + ni * 8 + 2 * c;              \
                    float2 b2 = *(const float2*)(bias + col);                        \
                    float2 v;                                                        \
                    v.x = acc[mi][ni][g2 * 2 + 0] + b2.x;                            \
                    v.y = acc[mi][ni][g2 * 2 + 1] + b2.y;                            \
                    if (EPI == 0) {                                                  \
                        const int which = (col >= 768) ? 2 : (col >= 384 ? 1 : 0);   \
                        const int ccc = col - which * 384;                           \
                        const int h = ccc >> 5, dd = ccc & 31;                       \
                        const size_t di =                                            \
                            ((size_t)(bb * 12 + h) * 49 + n) * 32 + dd;              \
                        if (which == 0) {                                            \
                            v.x *= 0.17677669529663689f;                             \
                            v.y *= 0.17677669529663689f;                             \
                            *(__half2*)(g_Qh + di) = __floats2half2_rn(v.x, v.y);    \
                        } else if (which == 1) {                                     \
                            *(__half2*)(g_Kh + di) = __floats2half2_rn(v.x, v.y);    \
                        } else {                                                     \
                            *(__half2*)(g_Vh + di) = __floats2half2_rn(v.x, v.y);    \
                        }                                                            \
                    } else {                                                         \
                        *(float2*)(out + (size_t)row * 384 + col) = v;               \
                    }                                                                \
                }                                                                    \
            }                                                                        \
        }                                                                            \
    } while (0)

    for (int g = 0; g < 24; g++) {
        // committed = 4 + min(g,20); need group g done
        if (g < 21) cp_wait<3>();
        else if (g == 21) cp_wait<2>();
        else if (g == 22) cp_wait<1>();
        else cp_wait<0>();
        __syncthreads();
        if (g + 4 < 24) { LOADSTG((g + 4) % NSTG, g + 4); cp_commit(); }

        const uint32_t sb = smem0 + (g % NSTG) * STG_B;
#pragma unroll
        for (int ks = 0; ks < 2; ks++) {
            unsigned af[4][4], bf[4][2];
#pragma unroll
            for (int mi = 0; mi < 4; mi++)
                ldsm4(af[mi], sb + (2 * ks) * 2048 + (wm * 64 + mi * 16) * 16 + a_lane);
#pragma unroll
            for (int p = 0; p < 2; p++) {
                unsigned t[4];
                ldsm4(t, sb + 8192 + (2 * ks) * 2048 + (wn * 32 + p * 16) * 16 + b_lane);
                bf[2 * p][0] = t[0]; bf[2 * p][1] = t[1];
                bf[2 * p + 1][0] = t[2]; bf[2 * p + 1][1] = t[3];
            }
#pragma unroll
            for (int mi = 0; mi < 4; mi++)
#pragma unroll
                for (int ni = 0; ni < 4; ni++) mma16(acc[mi][ni], af[mi], bf[ni]);
        }
        if (g == 11) {
            EPILOG(rowBase);
#pragma unroll
            for (int mi = 0; mi < 4; mi++)
#pragma unroll
                for (int ni = 0; ni < 4; ni++)
#pragma unroll
                    for (int k = 0; k < 4; k++) acc[mi][ni][k] = 0.f;
        }
        // stage-reuse safe: overwrite target (g+4)%5 == (g-1)%5; its readers
        // passed this iteration's top-of-loop barrier. Epilogue touches no smem.
    }

    EPILOG(rowBase + 128);
#undef LOADSTG
#undef EPILOG
}

// ---------------------------------------------------------------------------
// Register-resident tensor-core attention (unchanged — passing since R7).
// ---------------------------------------------------------------------------
#define AQ_STR 40

__global__ void __launch_bounds__(128) attn_mma() {
    __shared__ __half sQ[64 * AQ_STR];
    __shared__ __half sK[64 * AQ_STR];
    __shared__ __half sV[64 * AQ_STR];

    const int b = blockIdx.x;
    const int h = blockIdx.y;
    const int tid = threadIdx.x;
    const int lane = tid & 31;
    const int warp = tid >> 5;

    const __half* Qb = g_Qh + (size_t)(b * 12 + h) * 1568;
    const __half* Kb = g_Kh + (size_t)(b * 12 + h) * 1568;
    const __half* Vb = g_Vh + (size_t)(b * 12 + h) * 1568;

    {
        uint4 z = {0u, 0u, 0u, 0u};
        uint4* vp = (uint4*)(sV + 49 * AQ_STR);
        for (int i = tid; i < 75; i += 128) vp[i] = z;
    }

    for (int f = tid; f < 196; f += 128) {
        const int row = f >> 2, ch = (f & 3) * 8;
        *(uint4*)&sQ[row * AQ_STR + ch] = *(const uint4*)(Qb + row * 32 + ch);
        *(uint4*)&sK[row * AQ_STR + ch] = *(const uint4*)(Kb + row * 32 + ch);
        *(uint4*)&sV[row * AQ_STR + ch] = *(const uint4*)(Vb + row * 32 + ch);
    }
    __syncthreads();

    const int r = lane >> 2, c = lane & 3;
    const int lr = lane & 7, sel = lane >> 3;
    const float* bm = g_BM + ((size_t)(b & 63) * 12 + h) * 2401;

    const uint32_t sQb = s2u(sQ), sKb = s2u(sK), sVb = s2u(sV);
    const uint32_t qp_lane80 = (uint32_t)((lr + (sel & 1) * 8) * 80 + (sel >> 1) * 16);
    const uint32_t k_lane80  = (uint32_t)((((sel >> 1) * 8) + lr) * 80 + (sel & 1) * 16);
    const uint32_t v_lane80  = (uint32_t)((lr + ((lane >> 3) & 1) * 8) * 80);

    const int m0 = warp * 16;
    unsigned aQ[2][4];
#pragma unroll
    for (int ks = 0; ks < 2; ks++)
        ldsm4(aQ[ks], sQb + m0 * 80 + ks * 32 + qp_lane80);

    unsigned bK[2][4][4];
#pragma unroll
    for (int ks = 0; ks < 2; ks++)
#pragma unroll
        for (int st = 0; st < 4; st++)
            ldsm4(bK[ks][st], sKb + st * 16 * 80 + ks * 32 + k_lane80);

    float acc[8][4];
#pragma unroll
    for (int nt = 0; nt < 8; nt++)
#pragma unroll
        for (int j = 0; j < 4; j++) acc[nt][j] = 0.f;

#pragma unroll
    for (int ks = 0; ks < 2; ks++)
#pragma unroll
        for (int st = 0; st < 4; st++) {
            mma16(acc[st * 2 + 0], aQ[ks], &bK[ks][st][0]);
            mma16(acc[st * 2 + 1], aQ[ks], &bK[ks][st][2]);
        }

    const int row0 = m0 + r;
    const int row1 = row0 + 8;
    const int rc0 = (row0 < 49 ? row0 : 48) * 49;
    const int rc1 = (row1 < 49 ? row1 : 48) * 49;

    float mx0 = -3.0e38f, mx1 = -3.0e38f;
#pragma unroll
    for (int nt = 0; nt < 8; nt++) {
        const int col = nt * 8 + 2 * c;
        acc[nt][0] = (col < 49)     ? acc[nt][0] + bm[rc0 + col]     : -1e30f;
        acc[nt][1] = (col + 1 < 49) ? acc[nt][1] + bm[rc0 + col + 1] : -1e30f;
        acc[nt][2] = (col < 49)     ? acc[nt][2] + bm[rc1 + col]     : -1e30f;
        acc[nt][3] = (col + 1 < 49) ? acc[nt][3] + bm[rc1 + col + 1] : -1e30f;
        mx0 = fmaxf(mx0, fmaxf(acc[nt][0], acc[nt][1]));
        mx1 = fmaxf(mx1, fmaxf(acc[nt][2], acc[nt][3]));
    }
    mx0 = fmaxf(mx0, __shfl_xor_sync(0xffffffffu, mx0, 1));
    mx0 = fmaxf(mx0, __shfl_xor_sync(0xffffffffu, mx0, 2));
    mx1 = fmaxf(mx1, __shfl_xor_sync(0xffffffffu, mx1, 1));
    mx1 = fmaxf(mx1, __shfl_xor_sync(0xffffffffu, mx1, 2));

    float sm0 = 0.f, sm1 = 0.f;
#pragma unroll
    for (int nt = 0; nt < 8; nt++) {
        acc[nt][0] = __expf(acc[nt][0] - mx0);
        acc[nt][1] = __expf(acc[nt][1] - mx0);
        acc[nt][2] = __expf(acc[nt][2] - mx1);
        acc[nt][3] = __expf(acc[nt][3] - mx1);
        sm0 += acc[nt][0] + acc[nt][1];
        sm1 += acc[nt][2] + acc[nt][3];
    }
    sm0 += __shfl_xor_sync(0xffffffffu, sm0, 1);
    sm0 += __shfl_xor_sync(0xffffffffu, sm0, 2);
    sm1 += __shfl_xor_sync(0xffffffffu, sm1, 1);
    sm1 += __shfl_xor_sync(0xffffffffu, sm1, 2);
    const float inv0 = 1.f / sm0;
    const float inv1 = 1.f / sm1;

    unsigned pA[8], pB[8];
#pragma unroll
    for (int nt = 0; nt < 8; nt++) {
        pA[nt] = pack_h2(acc[nt][0] * inv0, acc[nt][1] * inv0);
        pB[nt] = pack_h2(acc[nt][2] * inv1, acc[nt][3] * inv1);
    }

    unsigned bV[4][4][2];
#pragma unroll
    for (int j = 0; j < 4; j++)
#pragma unroll
        for (int nt = 0; nt < 4; nt++)
            ldsm2t(bV[j][nt], sVb + j * 16 * 80 + v_lane80 + nt * 16);

    float oacc[4][4];
#pragma unroll
    for (int nt = 0; nt < 4; nt++)
#pragma unroll
        for (int j = 0; j < 4; j++) oacc[nt][j] = 0.f;

#pragma unroll
    for (int j = 0; j < 4; j++) {
        unsigned a[4] = {pA[2 * j], pB[2 * j], pA[2 * j + 1], pB[2 * j + 1]};
#pragma unroll
        for (int nt = 0; nt < 4; nt++) mma16(oacc[nt], a, bV[j][nt]);
    }

    __half* AOb = g_AOh + (size_t)b * 49 * 384 + h * 32;
#pragma unroll
    for (int nt = 0; nt < 4; nt++) {
        const int col = nt * 8 + 2 * c;
        if (row0 < 49)
            *(__half2*)&AOb[row0 * 384 + col] = __floats2half2_rn(oacc[nt][0], oacc[nt][1]);
        if (row1 < 49)
            *(__half2*)&AOb[row1 * 384 + col] = __floats2half2_rn(oacc[nt][2], oacc[nt][3]);
    }
}

// ---------------------------------------------------------------------------
extern "C" void kernel_launch(void* const* d_in, const int* in_sizes, int n_in,
                              void* d_out, int out_size) {
    const float* x          = (const float*)d_in[0];
    const float* mask       = (const float*)d_in[1];
    const float* qkv_w      = (const float*)d_in[2];
    const float* qkv_b      = (const float*)d_in[3];
    const float* proj_w     = (const float*)d_in[4];
    const float* proj_b     = (const float*)d_in[5];
    const float* bias_table = (const float*)d_in[6];
    const int*   rel_idx    = (const int*)d_in[7];
    float*       out        = (float*)d_out;

    cudaFuncSetAttribute(gemm_h<0>, cudaFuncAttributeMaxDynamicSharedMemorySize, DYNSZ);
    cudaFuncSetAttribute(gemm_h<1>, cudaFuncAttributeMaxDynamicSharedMemorySize, DYNSZ);

    prep_all<<<14848, 384>>>(x, qkv_w, proj_w, mask, bias_table, rel_idx);

    gemm_h<0><<<dim3(9, 392), 256, DYNSZ>>>(qkv_b, nullptr);

    attn_mma<<<dim3(2048, 12), 128>>>();

    gemm_h<1><<<dim3(3, 392), 256, DYNSZ>>>(proj_b, out);
}

// round 17
// speedup vs baseline: 1.1324x; 1.1324x over previous
#include <cuda_runtime.h>
#include <cuda_fp16.h>
#include <cstdint>

#define BW    2048
#define NTOK  49
#define CDIM  384
#define HEADS 12
#define HD    32
#define NWIN  64

// ---------------------------------------------------------------------------
// Device scratch (allocation-free)
// ---------------------------------------------------------------------------
__device__ __half g_Xh [BW * NTOK * CDIM];          // x, fp16
__device__ __half g_AOh[BW * NTOK * CDIM];          // attention output, fp16
__device__ __half g_W1h[1152 * 384];                // qkv_w^T  [n][k] fp16
__device__ __half g_W2h[384 * 384];                 // proj_w^T [n][k] fp16
__device__ __half g_Qh[BW * HEADS * NTOK * HD];     // fp16, pre-scaled
__device__ __half g_Kh[BW * HEADS * NTOK * HD];
__device__ __half g_Vh[BW * HEADS * NTOK * HD];
__device__ float  g_BM[NWIN * HEADS * NTOK * NTOK]; // bias[rel_idx] + mask

// ---------------------------------------------------------------------------
// Helpers
// ---------------------------------------------------------------------------
__device__ __forceinline__ uint32_t s2u(const void* p) {
    uint32_t a;
    asm("{ .reg .u64 t; cvta.to.shared.u64 t, %1; cvt.u32.u64 %0, t; }"
        : "=r"(a) : "l"(p));
    return a;
}

__device__ __forceinline__ void cp16(uint32_t saddr, const void* g) {
    asm volatile("cp.async.cg.shared.global [%0], [%1], 16;"
                 :: "r"(saddr), "l"(g) : "memory");
}
__device__ __forceinline__ void cp_commit() {
    asm volatile("cp.async.commit_group;" ::: "memory");
}
template <int N>
__device__ __forceinline__ void cp_wait() {
    asm volatile("cp.async.wait_group %0;" :: "n"(N) : "memory");
}

// Non-volatile: lets ptxas reorder MMAs against next step's LDSMs (R15: neutral-safe).
__device__ __forceinline__ void mma16(float* cc, const unsigned* a, const unsigned* b) {
    asm("mma.sync.aligned.m16n8k16.row.col.f32.f16.f16.f32 "
        "{%0,%1,%2,%3}, {%4,%5,%6,%7}, {%8,%9}, {%0,%1,%2,%3};"
        : "+f"(cc[0]), "+f"(cc[1]), "+f"(cc[2]), "+f"(cc[3])
        : "r"(a[0]), "r"(a[1]), "r"(a[2]), "r"(a[3]), "r"(b[0]), "r"(b[1]));
}

__device__ __forceinline__ void ldsm4(unsigned* d, uint32_t a) {
    asm volatile("ldmatrix.sync.aligned.m8n8.x4.shared.b16 {%0,%1,%2,%3}, [%4];"
                 : "=r"(d[0]), "=r"(d[1]), "=r"(d[2]), "=r"(d[3]) : "r"(a));
}
__device__ __forceinline__ void ldsm2t(unsigned* d, uint32_t a) {
    asm volatile("ldmatrix.sync.aligned.m8n8.x2.trans.shared.b16 {%0,%1}, [%2];"
                 : "=r"(d[0]), "=r"(d[1]) : "r"(a));
}

__device__ __forceinline__ unsigned pack_h2(float a, float b) {
    __half2 h = __floats2half2_rn(a, b);
    return *reinterpret_cast<unsigned*>(&h);
}

// ---------------------------------------------------------------------------
// Merged prep kernel.
// blocks [0, 12544): convert x -> fp16, 2 float4 reads -> 1 uint4 store/thread
// blocks [12544, 14080): weight transpose
// blocks [14080, 14848): bias+mask table
// ---------------------------------------------------------------------------
#define XB_XH 12544
#define XB_WT (XB_XH + 1536)

__global__ void __launch_bounds__(384) prep_all(const float* __restrict__ x,
                                                const float* __restrict__ w1,
                                                const float* __restrict__ w2,
                                                const float* __restrict__ mask,
                                                const float* __restrict__ bt,
                                                const int* __restrict__ ri) {
    const int blk = blockIdx.x;
    if (blk < XB_XH) {
        const int i = blk * 384 + threadIdx.x;       // 0 .. 4816895
        float4 a = ((const float4*)x)[2 * i];
        float4 b = ((const float4*)x)[2 * i + 1];
        uint4 o;
        o.x = pack_h2(a.x, a.y);
        o.y = pack_h2(a.z, a.w);
        o.z = pack_h2(b.x, b.y);
        o.w = pack_h2(b.z, b.w);
        ((uint4*)g_Xh)[i] = o;
    } else if (blk < XB_WT) {
        const int b2 = blk - XB_XH;                  // 0..1535
        const int k = threadIdx.x;
        if (b2 < 1152) {
            g_W1h[b2 * 384 + k] = __float2half_rn(w1[k * 1152 + b2]);
        } else {
            const int n = b2 - 1152;
            g_W2h[n * 384 + k] = __float2half_rn(w2[k * 384 + n]);
        }
    } else {
        const int b3 = blk - XB_WT;                  // 0..767
        const int w = b3 & 63, h = b3 >> 6;
        float* dst = g_BM + (w * HEADS + h) * (NTOK * NTOK);
        const float* mw = mask + w * (NTOK * NTOK);
        for (int i = threadIdx.x; i < NTOK * NTOK; i += 384)
            dst[i] = bt[ri[i] * HEADS + h] + mw[i];
    }
}

// ---------------------------------------------------------------------------
// fp16 mma.sync GEMM — R13 proven-best configuration.
// BK=32, 4-stage cp.async ring, prefetch distance 3, .cg only.
// BM=128, BN=128; 256 threads, 8 warps (2m x 4n), warp tile 64x32.
// __launch_bounds__(256,2) -> 2 CTAs/SM. One 128-row tile per CTA.
// ---------------------------------------------------------------------------
#define STG_B  16384      // A 8KB + B 8KB per stage
#define NSTG   4
#define DYNSZ  (NSTG * STG_B)

template <int EPI>
__global__ void __launch_bounds__(256, 2) gemm_h(const float* __restrict__ bias,
                                                 float* __restrict__ out) {
    extern __shared__ char smem[];
    const uint32_t smem0 = s2u(smem);

    const __half* A  = (EPI == 0) ? g_Xh : g_AOh;
    const __half* Bw = (EPI == 0) ? (const __half*)g_W1h : (const __half*)g_W2h;

    const int tid  = threadIdx.x;
    const int lane = tid & 31;
    const int warp = tid >> 5;
    const int wm   = warp >> 2;           // 0..1 -> m = wm*64
    const int wn   = warp & 3;            // 0..3 -> n = wn*32
    const int colBase = blockIdx.x * 128;
    const int rowBase = blockIdx.y * 128;

    const __half* Ag = A + (size_t)rowBase * 384;
    const __half* Bg = Bw + (size_t)colBase * 384;

    const int r0 = tid >> 2,          c0 = tid & 3;
    const int r1 = (tid + 256) >> 2,  c1 = (tid + 256) & 3;

#define LOADSTG(s, kt)                                                          \
    do {                                                                        \
        const uint32_t sb = smem0 + (s) * STG_B;                                \
        cp16(sb + c0 * 2048 + r0 * 16, Ag + r0 * 384 + (kt) * 32 + c0 * 8);     \
        cp16(sb + c1 * 2048 + r1 * 16, Ag + r1 * 384 + (kt) * 32 + c1 * 8);     \
        cp16(sb + 8192 + c0 * 2048 + r0 * 16,                                   \
             Bg + r0 * 384 + (kt) * 32 + c0 * 8);                               \
        cp16(sb + 8192 + c1 * 2048 + r1 * 16,                                   \
             Bg + r1 * 384 + (kt) * 32 + c1 * 8);                               \
    } while (0)

    float acc[4][4][4];
#pragma unroll
    for (int mi = 0; mi < 4; mi++)
#pragma unroll
        for (int ni = 0; ni < 4; ni++)
#pragma unroll
            for (int k = 0; k < 4; k++) acc[mi][ni][k] = 0.f;

    LOADSTG(0, 0);
    cp_commit();
    LOADSTG(1, 1);
    cp_commit();
    LOADSTG(2, 2);
    cp_commit();

    const int r = lane >> 2;
    const int c = lane & 3;
    const int lr = lane & 7, sel = lane >> 3;
    const uint32_t a_lane = (uint32_t)((lr + (sel & 1) * 8) * 16 + (sel >> 1) * 2048);
    const uint32_t b_lane = (uint32_t)(((sel >> 1) * 8 + lr) * 16 + (sel & 1) * 2048);

    for (int kt = 0; kt < 12; kt++) {
        if (kt < 10) cp_wait<2>(); else if (kt == 10) cp_wait<1>(); else cp_wait<0>();
        __syncthreads();
        if (kt + 3 < 12) { LOADSTG((kt + 3) % NSTG, kt + 3); cp_commit(); }

        const uint32_t sb = smem0 + (kt % NSTG) * STG_B;
#pragma unroll
        for (int ks = 0; ks < 2; ks++) {
            unsigned af[4][4], bf[4][2];
#pragma unroll
            for (int mi = 0; mi < 4; mi++)
                ldsm4(af[mi], sb + (2 * ks) * 2048 + (wm * 64 + mi * 16) * 16 + a_lane);
#pragma unroll
            for (int p = 0; p < 2; p++) {
                unsigned t[4];
                ldsm4(t, sb + 8192 + (2 * ks) * 2048 + (wn * 32 + p * 16) * 16 + b_lane);
                bf[2 * p][0] = t[0]; bf[2 * p][1] = t[1];
                bf[2 * p + 1][0] = t[2]; bf[2 * p + 1][1] = t[3];
            }
#pragma unroll
            for (int mi = 0; mi < 4; mi++)
#pragma unroll
                for (int ni = 0; ni < 4; ni++) mma16(acc[mi][ni], af[mi], bf[ni]);
        }
        // no trailing sync: at iter kt we overwrite stage (kt+3)%4 == (kt-1)%4,
        // whose readers all passed this iteration's top-of-loop barrier.
    }

    // -------- epilogue
#pragma unroll
    for (int mi = 0; mi < 4; mi++) {
#pragma unroll
        for (int g = 0; g < 2; g++) {
            const int row = rowBase + wm * 64 + mi * 16 + r + g * 8;
            int bb = 0, n = 0;
            if (EPI == 0) { bb = row / 49; n = row - bb * 49; }
#pragma unroll
            for (int ni = 0; ni < 4; ni++) {
                const int col = colBase + wn * 32 + ni * 8 + 2 * c;
                float2 b2 = *(const float2*)(bias + col);
                float2 v;
                v.x = acc[mi][ni][g * 2 + 0] + b2.x;
                v.y = acc[mi][ni][g * 2 + 1] + b2.y;
                if (EPI == 0) {
                    const int which = (col >= 768) ? 2 : (col >= 384 ? 1 : 0);
                    const int ccc = col - which * 384;
                    const int h = ccc >> 5, dd = ccc & 31;
                    const size_t di = ((size_t)(bb * 12 + h) * 49 + n) * 32 + dd;
                    if (which == 0) {
                        v.x *= 0.17677669529663689f;
                        v.y *= 0.17677669529663689f;
                        *(__half2*)(g_Qh + di) = __floats2half2_rn(v.x, v.y);
                    } else if (which == 1) {
                        *(__half2*)(g_Kh + di) = __floats2half2_rn(v.x, v.y);
                    } else {
                        *(__half2*)(g_Vh + di) = __floats2half2_rn(v.x, v.y);
                    }
                } else {
                    *(float2*)(out + (size_t)row * 384 + col) = v;
                }
            }
        }
    }
#undef LOADSTG
}

// ---------------------------------------------------------------------------
// Register-resident tensor-core attention (unchanged — passing since R7).
// ---------------------------------------------------------------------------
#define AQ_STR 40

__global__ void __launch_bounds__(128) attn_mma() {
    __shared__ __half sQ[64 * AQ_STR];
    __shared__ __half sK[64 * AQ_STR];
    __shared__ __half sV[64 * AQ_STR];

    const int b = blockIdx.x;
    const int h = blockIdx.y;
    const int tid = threadIdx.x;
    const int lane = tid & 31;
    const int warp = tid >> 5;

    const __half* Qb = g_Qh + (size_t)(b * 12 + h) * 1568;
    const __half* Kb = g_Kh + (size_t)(b * 12 + h) * 1568;
    const __half* Vb = g_Vh + (size_t)(b * 12 + h) * 1568;

    {
        uint4 z = {0u, 0u, 0u, 0u};
        uint4* vp = (uint4*)(sV + 49 * AQ_STR);
        for (int i = tid; i < 75; i += 128) vp[i] = z;
    }

    for (int f = tid; f < 196; f += 128) {
        const int row = f >> 2, ch = (f & 3) * 8;
        *(uint4*)&sQ[row * AQ_STR + ch] = *(const uint4*)(Qb + row * 32 + ch);
        *(uint4*)&sK[row * AQ_STR + ch] = *(const uint4*)(Kb + row * 32 + ch);
        *(uint4*)&sV[row * AQ_STR + ch] = *(const uint4*)(Vb + row * 32 + ch);
    }
    __syncthreads();

    const int r = lane >> 2, c = lane & 3;
    const int lr = lane & 7, sel = lane >> 3;
    const float* bm = g_BM + ((size_t)(b & 63) * 12 + h) * 2401;

    const uint32_t sQb = s2u(sQ), sKb = s2u(sK), sVb = s2u(sV);
    const uint32_t qp_lane80 = (uint32_t)((lr + (sel & 1) * 8) * 80 + (sel >> 1) * 16);
    const uint32_t k_lane80  = (uint32_t)((((sel >> 1) * 8) + lr) * 80 + (sel & 1) * 16);
    const uint32_t v_lane80  = (uint32_t)((lr + ((lane >> 3) & 1) * 8) * 80);

    const int m0 = warp * 16;
    unsigned aQ[2][4];
#pragma unroll
    for (int ks = 0; ks < 2; ks++)
        ldsm4(aQ[ks], sQb + m0 * 80 + ks * 32 + qp_lane80);

    unsigned bK[2][4][4];
#pragma unroll
    for (int ks = 0; ks < 2; ks++)
#pragma unroll
        for (int st = 0; st < 4; st++)
            ldsm4(bK[ks][st], sKb + st * 16 * 80 + ks * 32 + k_lane80);

    float acc[8][4];
#pragma unroll
    for (int nt = 0; nt < 8; nt++)
#pragma unroll
        for (int j = 0; j < 4; j++) acc[nt][j] = 0.f;

#pragma unroll
    for (int ks = 0; ks < 2; ks++)
#pragma unroll
        for (int st = 0; st < 4; st++) {
            mma16(acc[st * 2 + 0], aQ[ks], &bK[ks][st][0]);
            mma16(acc[st * 2 + 1], aQ[ks], &bK[ks][st][2]);
        }

    const int row0 = m0 + r;
    const int row1 = row0 + 8;
    const int rc0 = (row0 < 49 ? row0 : 48) * 49;
    const int rc1 = (row1 < 49 ? row1 : 48) * 49;

    float mx0 = -3.0e38f, mx1 = -3.0e38f;
#pragma unroll
    for (int nt = 0; nt < 8; nt++) {
        const int col = nt * 8 + 2 * c;
        acc[nt][0] = (col < 49)     ? acc[nt][0] + bm[rc0 + col]     : -1e30f;
        acc[nt][1] = (col + 1 < 49) ? acc[nt][1] + bm[rc0 + col + 1] : -1e30f;
        acc[nt][2] = (col < 49)     ? acc[nt][2] + bm[rc1 + col]     : -1e30f;
        acc[nt][3] = (col + 1 < 49) ? acc[nt][3] + bm[rc1 + col + 1] : -1e30f;
        mx0 = fmaxf(mx0, fmaxf(acc[nt][0], acc[nt][1]));
        mx1 = fmaxf(mx1, fmaxf(acc[nt][2], acc[nt][3]));
    }
    mx0 = fmaxf(mx0, __shfl_xor_sync(0xffffffffu, mx0, 1));
    mx0 = fmaxf(mx0, __shfl_xor_sync(0xffffffffu, mx0, 2));
    mx1 = fmaxf(mx1, __shfl_xor_sync(0xffffffffu, mx1, 1));
    mx1 = fmaxf(mx1, __shfl_xor_sync(0xffffffffu, mx1, 2));

    float sm0 = 0.f, sm1 = 0.f;
#pragma unroll
    for (int nt = 0; nt < 8; nt++) {
        acc[nt][0] = __expf(acc[nt][0] - mx0);
        acc[nt][1] = __expf(acc[nt][1] - mx0);
        acc[nt][2] = __expf(acc[nt][2] - mx1);
        acc[nt][3] = __expf(acc[nt][3] - mx1);
        sm0 += acc[nt][0] + acc[nt][1];
        sm1 += acc[nt][2] + acc[nt][3];
    }
    sm0 += __shfl_xor_sync(0xffffffffu, sm0, 1);
    sm0 += __shfl_xor_sync(0xffffffffu, sm0, 2);
    sm1 += __shfl_xor_sync(0xffffffffu, sm1, 1);
    sm1 += __shfl_xor_sync(0xffffffffu, sm1, 2);
    const float inv0 = 1.f / sm0;
    const float inv1 = 1.f / sm1;

    unsigned pA[8], pB[8];
#pragma unroll
    for (int nt = 0; nt < 8; nt++) {
        pA[nt] = pack_h2(acc[nt][0] * inv0, acc[nt][1] * inv0);
        pB[nt] = pack_h2(acc[nt][2] * inv1, acc[nt][3] * inv1);
    }

    unsigned bV[4][4][2];
#pragma unroll
    for (int j = 0; j < 4; j++)
#pragma unroll
        for (int nt = 0; nt < 4; nt++)
            ldsm2t(bV[j][nt], sVb + j * 16 * 80 + v_lane80 + nt * 16);

    float oacc[4][4];
#pragma unroll
    for (int nt = 0; nt < 4; nt++)
#pragma unroll
        for (int j = 0; j < 4; j++) oacc[nt][j] = 0.f;

#pragma unroll
    for (int j = 0; j < 4; j++) {
        unsigned a[4] = {pA[2 * j], pB[2 * j], pA[2 * j + 1], pB[2 * j + 1]};
#pragma unroll
        for (int nt = 0; nt < 4; nt++) mma16(oacc[nt], a, bV[j][nt]);
    }

    __half* AOb = g_AOh + (size_t)b * 49 * 384 + h * 32;
#pragma unroll
    for (int nt = 0; nt < 4; nt++) {
        const int col = nt * 8 + 2 * c;
        if (row0 < 49)
            *(__half2*)&AOb[row0 * 384 + col] = __floats2half2_rn(oacc[nt][0], oacc[nt][1]);
        if (row1 < 49)
            *(__half2*)&AOb[row1 * 384 + col] = __floats2half2_rn(oacc[nt][2], oacc[nt][3]);
    }
}

// ---------------------------------------------------------------------------
extern "C" void kernel_launch(void* const* d_in, const int* in_sizes, int n_in,
                              void* d_out, int out_size) {
    const float* x          = (const float*)d_in[0];
    const float* mask       = (const float*)d_in[1];
    const float* qkv_w      = (const float*)d_in[2];
    const float* qkv_b      = (const float*)d_in[3];
    const float* proj_w     = (const float*)d_in[4];
    const float* proj_b     = (const float*)d_in[5];
    const float* bias_table = (const float*)d_in[6];
    const int*   rel_idx    = (const int*)d_in[7];
    float*       out        = (float*)d_out;

    cudaFuncSetAttribute(gemm_h<0>, cudaFuncAttributeMaxDynamicSharedMemorySize, DYNSZ);
    cudaFuncSetAttribute(gemm_h<1>, cudaFuncAttributeMaxDynamicSharedMemorySize, DYNSZ);

    prep_all<<<14848, 384>>>(x, qkv_w, proj_w, mask, bias_table, rel_idx);

    gemm_h<0><<<dim3(9, 784), 256, DYNSZ>>>(qkv_b, nullptr);

    attn_mma<<<dim3(2048, 12), 128>>>();

    gemm_h<1><<<dim3(3, 784), 256, DYNSZ>>>(proj_b, out);
}